// round 3
// baseline (speedup 1.0000x reference)
#include <cuda_runtime.h>
#include <cstdint>

// Problem dims
#define NB 32
#define C  64
#define H  128
#define W  128
#define CO 64
#define HO 64
#define WO 64

// Scratch (no cudaMalloc allowed): packed sign bits.
// g_xpack[n][h][w] : 64 channel sign bits (bit c = x[n,c,h,w] >= 0)
__device__ uint64_t g_xpack[NB * H * W];          // 4 MiB
// g_wpack[co*9 + ky*3 + kx] : 64 input-channel sign bits
__device__ uint64_t g_wpack[CO * 9];

// ---------------------------------------------------------------------------
// Kernel 1: pack x sign bits. Thread handles 4 consecutive w pixels,
// loops over 64 channels with coalesced float4 loads.
// ---------------------------------------------------------------------------
__global__ __launch_bounds__(256) void pack_x_kernel(const float* __restrict__ x) {
    int tid = blockIdx.x * blockDim.x + threadIdx.x;   // 0 .. 131071
    int w4 = tid & 31;            // group of 4 pixels along w
    int h  = (tid >> 5) & 127;
    int n  = tid >> 12;

    const float* base = x + (size_t)n * C * (H * W) + h * W + w4 * 4;

    uint32_t lo0 = 0, lo1 = 0, lo2 = 0, lo3 = 0;
    uint32_t hi0 = 0, hi1 = 0, hi2 = 0, hi3 = 0;

    #pragma unroll 8
    for (int c = 0; c < 32; ++c) {
        float4 v = *reinterpret_cast<const float4*>(base + (size_t)c * (H * W));
        lo0 |= (uint32_t)(v.x >= 0.0f) << c;
        lo1 |= (uint32_t)(v.y >= 0.0f) << c;
        lo2 |= (uint32_t)(v.z >= 0.0f) << c;
        lo3 |= (uint32_t)(v.w >= 0.0f) << c;
    }
    #pragma unroll 8
    for (int c = 0; c < 32; ++c) {
        float4 v = *reinterpret_cast<const float4*>(base + (size_t)(c + 32) * (H * W));
        hi0 |= (uint32_t)(v.x >= 0.0f) << c;
        hi1 |= (uint32_t)(v.y >= 0.0f) << c;
        hi2 |= (uint32_t)(v.z >= 0.0f) << c;
        hi3 |= (uint32_t)(v.w >= 0.0f) << c;
    }

    uint64_t* op = g_xpack + ((size_t)n * H + h) * W + w4 * 4;
    op[0] = (uint64_t)lo0 | ((uint64_t)hi0 << 32);
    op[1] = (uint64_t)lo1 | ((uint64_t)hi1 << 32);
    op[2] = (uint64_t)lo2 | ((uint64_t)hi2 << 32);
    op[3] = (uint64_t)lo3 | ((uint64_t)hi3 << 32);
}

// ---------------------------------------------------------------------------
// Kernel 2: pack w sign bits. One block, one thread per (co, tap).
// w is OIHW (64,64,3,3).
// ---------------------------------------------------------------------------
__global__ void pack_w_kernel(const float* __restrict__ w) {
    int t = threadIdx.x;
    if (t >= CO * 9) return;
    int co = t / 9;
    int k  = t - co * 9;   // ky*3+kx
    uint32_t lo = 0, hi = 0;
    #pragma unroll 8
    for (int ci = 0; ci < 32; ++ci)
        lo |= (uint32_t)(w[(size_t)(co * 64 + ci) * 9 + k] >= 0.0f) << ci;
    #pragma unroll 8
    for (int ci = 0; ci < 32; ++ci)
        hi |= (uint32_t)(w[(size_t)(co * 64 + ci + 32) * 9 + k] >= 0.0f) << ci;
    g_wpack[t] = (uint64_t)lo | ((uint64_t)hi << 32);
}

// ---------------------------------------------------------------------------
// Kernel 3: XNOR-popcount conv.
// Block = (n, 4 output rows). 256 threads: tx = wo (0..63), ty = local ho (0..3).
// Stages the 9x129 packed-input patch + all 576 weight words in shared,
// then each thread loops over 64 c_out reusing its 9 registers of x bits.
// out[n][co][ho][wo] = 64*nvalid - 2 * sum_t popc((s_t ^ wb_t) & m_t)
// ---------------------------------------------------------------------------
__global__ __launch_bounds__(256) void qconv_kernel(float* __restrict__ out) {
    const int PW = 132;                     // padded patch row width (words)
    __shared__ uint64_t sw[CO * 9];         // 4608 B
    __shared__ uint64_t sp[9 * 132];        // 9504 B

    int n   = blockIdx.y;
    int ho0 = blockIdx.x * 4;
    int iy0 = 2 * ho0 - 1;

    // Stage input patch: rows iy0..iy0+8, cols -1..127 (129 words/row)
    for (int i = threadIdx.x; i < 9 * 129; i += 256) {
        int r  = i / 129;
        int cx = i - r * 129;
        int iy = iy0 + r;
        int ix = cx - 1;
        uint64_t v = 0;
        if (iy >= 0 && ix >= 0)             // upper bounds always in range
            v = g_xpack[((size_t)n * H + iy) * W + ix];
        sp[r * PW + cx] = v;
    }
    // Stage weights
    for (int i = threadIdx.x; i < CO * 9; i += 256)
        sw[i] = g_wpack[i];
    __syncthreads();

    int tx = threadIdx.x & 63;    // wo
    int ty = threadIdx.x >> 6;    // local ho
    int ho = ho0 + ty;

    // Gather this thread's 9 input words + validity masks into registers
    uint32_t slo[9], shi[9], msk[9];
    #pragma unroll
    for (int ky = 0; ky < 3; ++ky) {
        #pragma unroll
        for (int kx = 0; kx < 3; ++kx) {
            int t = ky * 3 + kx;
            uint64_t s = sp[(2 * ty + ky) * PW + 2 * tx + kx];
            slo[t] = (uint32_t)s;
            shi[t] = (uint32_t)(s >> 32);
            bool valid = (ho > 0 || ky > 0) && (tx > 0 || kx > 0);
            msk[t] = valid ? 0xFFFFFFFFu : 0u;
        }
    }
    int nvalid = (ho > 0 ? 3 : 2) * (tx > 0 ? 3 : 2);
    int base   = 64 * nvalid;

    float* op = out + (((size_t)n * CO) * HO + ho) * WO + tx;

    #pragma unroll 2
    for (int co = 0; co < CO; ++co) {
        const uint64_t* wrow = sw + co * 9;
        int acc = 0;
        #pragma unroll
        for (int t = 0; t < 9; ++t) {
            uint64_t wv = wrow[t];                 // warp-uniform broadcast LDS
            acc += __popc((slo[t] ^ (uint32_t)wv) & msk[t]);
            acc += __popc((shi[t] ^ (uint32_t)(wv >> 32)) & msk[t]);
        }
        op[(size_t)co * (HO * WO)] = (float)(base - 2 * acc);
    }
}

// ---------------------------------------------------------------------------
extern "C" void kernel_launch(void* const* d_in, const int* in_sizes, int n_in,
                              void* d_out, int out_size) {
    const float* x = (const float*)d_in[0];
    const float* w = (const float*)d_in[1];
    float* out = (float*)d_out;

    pack_x_kernel<<<512, 256>>>(x);          // 131072 threads
    pack_w_kernel<<<1, 576>>>(w);
    qconv_kernel<<<dim3(16, NB), 256>>>(out);
}

// round 4
// speedup vs baseline: 1.0838x; 1.0838x over previous
#include <cuda_runtime.h>
#include <cstdint>

// Problem dims
#define NB 32
#define C  64
#define H  128
#define W  128
#define CO 64
#define HO 64
#define WO 64

// Scratch: packed sign bits.
// g_xpack[n][h][w] : 64 channel sign bits (bit c = x[n,c,h,w] >= 0)
__device__ uint64_t g_xpack[NB * H * W];          // 4 MiB
// g_wpack[co*9 + ky*3 + kx] : 64 input-channel sign bits
__device__ uint64_t g_wpack[CO * 9];

// ---------------------------------------------------------------------------
// Kernel 1: pack x sign bits. Thread handles 2 consecutive w pixels,
// loops over 64 channels with coalesced float2 loads. Grid = 1024 blocks
// (vs 512 before) to lift occupancy / MLP toward the HBM roofline.
// ---------------------------------------------------------------------------
__global__ __launch_bounds__(256) void pack_x_kernel(const float* __restrict__ x) {
    int tid = blockIdx.x * blockDim.x + threadIdx.x;   // 0 .. 262143
    int w2 = tid & 63;            // group of 2 pixels along w
    int h  = (tid >> 6) & 127;
    int n  = tid >> 13;

    const float* base = x + (size_t)n * C * (H * W) + h * W + w2 * 2;

    uint32_t lo0 = 0, lo1 = 0;
    uint32_t hi0 = 0, hi1 = 0;

    #pragma unroll 16
    for (int c = 0; c < 32; ++c) {
        float2 v = *reinterpret_cast<const float2*>(base + (size_t)c * (H * W));
        lo0 |= (uint32_t)(v.x >= 0.0f) << c;
        lo1 |= (uint32_t)(v.y >= 0.0f) << c;
    }
    #pragma unroll 16
    for (int c = 0; c < 32; ++c) {
        float2 v = *reinterpret_cast<const float2*>(base + (size_t)(c + 32) * (H * W));
        hi0 |= (uint32_t)(v.x >= 0.0f) << c;
        hi1 |= (uint32_t)(v.y >= 0.0f) << c;
    }

    uint64_t* op = g_xpack + ((size_t)n * H + h) * W + w2 * 2;
    op[0] = (uint64_t)lo0 | ((uint64_t)hi0 << 32);
    op[1] = (uint64_t)lo1 | ((uint64_t)hi1 << 32);
}

// ---------------------------------------------------------------------------
// Kernel 2: pack w sign bits — parallel + coalesced.
// 16 blocks x 288 threads. Block b handles 4 c_out (4*576 = 2304 floats):
// stage sign bytes to smem with coalesced global loads, then 36 threads
// gather their (co,tap) word from smem.
// ---------------------------------------------------------------------------
__global__ __launch_bounds__(288) void pack_w_kernel(const float* __restrict__ w) {
    __shared__ uint8_t s[4 * 576];
    int b = blockIdx.x;
    const float* wb = w + (size_t)b * (4 * 576);

    for (int i = threadIdx.x; i < 4 * 576; i += 288)
        s[i] = (uint8_t)(wb[i] >= 0.0f);
    __syncthreads();

    int t = threadIdx.x;
    if (t < 36) {
        int co_l = t / 9;
        int k    = t - co_l * 9;          // ky*3+kx
        const uint8_t* sc = s + co_l * 576 + k;
        uint32_t lo = 0, hi = 0;
        #pragma unroll 8
        for (int ci = 0; ci < 32; ++ci)
            lo |= (uint32_t)sc[ci * 9] << ci;
        #pragma unroll 8
        for (int ci = 0; ci < 32; ++ci)
            hi |= (uint32_t)sc[(ci + 32) * 9] << ci;
        g_wpack[(b * 4 + co_l) * 9 + k] = (uint64_t)lo | ((uint64_t)hi << 32);
    }
}

// ---------------------------------------------------------------------------
// Kernel 3: XNOR-popcount conv.
// Grid: (16 ho-groups, NB, 2 co-halves). Block = 256 threads:
// tx = wo (0..63), ty = local ho (0..3). Each block computes 32 c_out for
// a 4x64 output tile. Doubling the grid (512 -> 1024 blocks) balances the
// wave and gives the SMSPs enough warps to hide LDS/issue latency.
// out[n][co][ho][wo] = 64*nvalid - 2 * sum_t popc((s_t ^ wb_t) & m_t)
// ---------------------------------------------------------------------------
__global__ __launch_bounds__(256) void qconv_kernel(float* __restrict__ out) {
    const int PW = 132;                     // padded patch row width (words)
    __shared__ uint64_t sw[32 * 9];         // this block's 32-co weight half
    __shared__ uint64_t sp[9 * 132];        // input patch

    int n   = blockIdx.y;
    int ho0 = blockIdx.x * 4;
    int coh = blockIdx.z * 32;              // c_out half base
    int iy0 = 2 * ho0 - 1;

    // Stage input patch: rows iy0..iy0+8, cols -1..127 (129 words/row)
    for (int i = threadIdx.x; i < 9 * 129; i += 256) {
        int r  = i / 129;
        int cx = i - r * 129;
        int iy = iy0 + r;
        int ix = cx - 1;
        uint64_t v = 0;
        if (iy >= 0 && ix >= 0)             // upper bounds always in range
            v = g_xpack[((size_t)n * H + iy) * W + ix];
        sp[r * PW + cx] = v;
    }
    // Stage this half's weights
    for (int i = threadIdx.x; i < 32 * 9; i += 256)
        sw[i] = g_wpack[coh * 9 + i];
    __syncthreads();

    int tx = threadIdx.x & 63;    // wo
    int ty = threadIdx.x >> 6;    // local ho
    int ho = ho0 + ty;

    // Gather this thread's 9 input words + validity masks into registers
    uint32_t slo[9], shi[9], msk[9];
    #pragma unroll
    for (int ky = 0; ky < 3; ++ky) {
        #pragma unroll
        for (int kx = 0; kx < 3; ++kx) {
            int t = ky * 3 + kx;
            uint64_t s = sp[(2 * ty + ky) * PW + 2 * tx + kx];
            slo[t] = (uint32_t)s;
            shi[t] = (uint32_t)(s >> 32);
            bool valid = (ho > 0 || ky > 0) && (tx > 0 || kx > 0);
            msk[t] = valid ? 0xFFFFFFFFu : 0u;
        }
    }
    int nvalid = (ho > 0 ? 3 : 2) * (tx > 0 ? 3 : 2);
    int base   = 64 * nvalid;

    float* op = out + (((size_t)n * CO + coh) * HO + ho) * WO + tx;

    #pragma unroll 4
    for (int co = 0; co < 32; ++co) {
        const uint64_t* wrow = sw + co * 9;
        int acc = 0;
        #pragma unroll
        for (int t = 0; t < 9; ++t) {
            uint64_t wv = wrow[t];                 // warp-uniform broadcast LDS
            acc += __popc((slo[t] ^ (uint32_t)wv) & msk[t]);
            acc += __popc((shi[t] ^ (uint32_t)(wv >> 32)) & msk[t]);
        }
        op[(size_t)co * (HO * WO)] = (float)(base - 2 * acc);
    }
}

// ---------------------------------------------------------------------------
extern "C" void kernel_launch(void* const* d_in, const int* in_sizes, int n_in,
                              void* d_out, int out_size) {
    const float* x = (const float*)d_in[0];
    const float* w = (const float*)d_in[1];
    float* out = (float*)d_out;

    pack_x_kernel<<<1024, 256>>>(x);         // 262144 threads, 2 px each
    pack_w_kernel<<<16, 288>>>(w);
    qconv_kernel<<<dim3(16, NB, 2), 256>>>(out);
}